// round 8
// baseline (speedup 1.0000x reference)
#include <cuda_runtime.h>

// B3-spline à-trous UWT, J=3. ONE kernel launch: grid z = level*8 + image.
// (8,1024,1024) fp32 -> (8,4,1024,1024) fp32 = [w1,w2,w3,c3]
//
// Per block: one 64x64 tile of one level. Warp-autonomous 8-row strips.
// Phase 1 (vertical conv): each lane owns one 4-wide column and issues ALL
// 8+4D row loads as independent LDG.128s (high MLP), accumulating into 8
// float4 accs with compile-time tap weights, then stores the strip to smem.
// Phase 2: horizontal conv from smem + diff + coalesced store.
// Levels synchronize via per-image release/acquire counters (bid-ordered
// dispatch -> deadlock-free; counters self-reset -> graph-replay safe).
// c1 lives in out ch3 (overwritten by c3), c2 in a static scratch buffer.

namespace {

constexpr int NT  = 256;
constexpr int IMG = 1024;
constexpr size_t CHS = (size_t)IMG * IMG;

constexpr float W0 = 0.0625f;
constexpr float W1 = 0.25f;
constexpr float W2 = 0.375f;

__device__ float g_scratch[8u * 1024u * 1024u];  // 32MB c2 carrier
__device__ unsigned g_done[3][8];                // zero-init; self-resetting

__device__ __forceinline__ int refl(int g) {
    g = g < 0 ? -g : g;
    return g >= IMG ? 2 * IMG - 2 - g : g;
}
__device__ __forceinline__ float b3s(float a, float b, float c, float d, float e) {
    return fmaf(c, W2, fmaf(b + d, W1, (a + e) * W0));
}
__device__ __forceinline__ void st4(float* p, float4 v) {
    *reinterpret_cast<float4*>(p) = v;
}
__device__ __forceinline__ float4 ld4(const float* p) {
    return *reinterpret_cast<const float4*>(p);
}
__device__ __forceinline__ float4 lg4(const float* p) {
    return __ldg(reinterpret_cast<const float4*>(p));
}
__device__ __forceinline__ float4 gath(const float* row, const int cc[4]) {
    return make_float4(__ldg(row + cc[0]), __ldg(row + cc[1]),
                       __ldg(row + cc[2]), __ldg(row + cc[3]));
}
__device__ __forceinline__ void fma4(float4& a, float w, const float4& v) {
    a.x = fmaf(w, v.x, a.x);
    a.y = fmaf(w, v.y, a.y);
    a.z = fmaf(w, v.z, a.z);
    a.w = fmaf(w, v.w, a.w);
}

// One 64x64 tile of one level, dilation D. H = col halo (4 for D<=2, else
// 2D; 16B-aligned), NVEC = (64+2H)/4 vec-cols, PB = smem row pitch.
template <int D, int NVEC, int PB>
__device__ __forceinline__ void level_tile(const float* __restrict__ s,
                                           float* __restrict__ wd,
                                           float* __restrict__ cd,
                                           float* __restrict__ B) {
    const int tid  = threadIdx.x;
    const int lane = tid & 31;
    const int warp = tid >> 5;
    const int gc0 = blockIdx.x * 64;
    const int gr0 = blockIdx.y * 64;
    const int wr0 = gr0 + warp * 8;
    float* Bw = B + warp * (8 * PB);
    constexpr int H = (D == 1) ? 4 : 2 * D;
    constexpr int NROWS = 8 + 4 * D;     // input rows per strip
    const bool colint = (gc0 >= H) && (gc0 + 64 + H <= IMG);

    // ---- phase 1: vertical conv, accumulator form (independent loads) ----
    if (lane < NVEC) {
        const int cb = gc0 - H + 4 * lane;
        float* Bp = Bw + 4 * lane;
        float4 acc[8];
#pragma unroll
        for (int r = 0; r < 8; ++r) acc[r] = make_float4(0.f, 0.f, 0.f, 0.f);

        int cc[4];
        if (!colint) {
#pragma unroll
            for (int j = 0; j < 4; ++j) {
                int c = cb + j;
                c = c < 0 ? -c : c;
                cc[j] = c >= IMG ? 2 * IMG - 2 - c : c;
            }
        }
        const float* cp = s + cb;
#pragma unroll
        for (int k = 0; k < NROWS; ++k) {
            const size_t ro = (size_t)refl(wr0 - 2 * D + k) * IMG;
            const float4 v = colint ? lg4(cp + ro) : gath(s + ro, cc);
            if (k < 8)                          fma4(acc[k],          W0, v);
            if (k - D >= 0 && k - D < 8)        fma4(acc[k - D],      W1, v);
            if (k - 2 * D >= 0 && k - 2 * D < 8) fma4(acc[k - 2 * D], W2, v);
            if (k - 3 * D >= 0 && k - 3 * D < 8) fma4(acc[k - 3 * D], W1, v);
            if (k - 4 * D >= 0 && k - 4 * D < 8) fma4(acc[k - 4 * D], W0, v);
        }
#pragma unroll
        for (int r = 0; r < 8; ++r) st4(Bp + r * PB, acc[r]);
    }
    __syncwarp();

    // ---- phase 2: horizontal conv + diff + coalesced store ----
    const int v = lane & 15, sub = lane >> 4;
    constexpr int BL = H / 4;
    constexpr int NV = 2 * BL + 1;      // window float4 count (3/3/5)
    constexpr int C  = H;               // center float offset in window
#pragma unroll
    for (int i = 0; i < 4; ++i) {
        const int rr = i * 2 + sub;
        const float* Bp = Bw + rr * PB + 4 * v;
        float w[4 * NV];
#pragma unroll
        for (int k = 0; k < NV; ++k) {
            const float4 t = ld4(Bp + 4 * k);
            w[4 * k + 0] = t.x; w[4 * k + 1] = t.y;
            w[4 * k + 2] = t.z; w[4 * k + 3] = t.w;
        }
        float4 o;
        o.x = b3s(w[C - 2 * D],     w[C - D],     w[C],     w[C + D],     w[C + 2 * D]);
        o.y = b3s(w[C + 1 - 2 * D], w[C + 1 - D], w[C + 1], w[C + 1 + D], w[C + 1 + 2 * D]);
        o.z = b3s(w[C + 2 - 2 * D], w[C + 2 - D], w[C + 2], w[C + 2 + D], w[C + 2 + 2 * D]);
        o.w = b3s(w[C + 3 - 2 * D], w[C + 3 - D], w[C + 3], w[C + 3 + D], w[C + 3 + 2 * D]);

        const size_t go = (size_t)(wr0 + rr) * IMG + gc0 + 4 * v;
        const float4 a = lg4(s + go);
        st4(wd + go, make_float4(a.x - o.x, a.y - o.y, a.z - o.z, a.w - o.w));
        st4(cd + go, o);
    }
}

__device__ __forceinline__ void gate(unsigned* ctr) {
    if (threadIdx.x == 0) {
        while (atomicAdd(ctr, 0u) < 256u) __nanosleep(64);
        __threadfence();
    }
    __syncthreads();
}
__device__ __forceinline__ void finish(unsigned* ctr) {
    __threadfence();
    __syncthreads();
    if (threadIdx.x == 0) atomicAdd(ctr, 1u);
}

}  // namespace

__global__ void __launch_bounds__(NT, 4)
uwt_all_kernel(const float* __restrict__ x, float* __restrict__ out) {
    __shared__ float B[8 * 8 * 80];  // max strip pitch (D=4)
    const int z = blockIdx.z;
    const int l = z >> 3;
    const int b = z & 7;

    if (l == 0) {
        level_tile<1, 18, 72>(x + (size_t)b * CHS,
                              out + (size_t)(4 * b + 0) * CHS,
                              out + (size_t)(4 * b + 3) * CHS, B);
        finish(&g_done[0][b]);
    } else if (l == 1) {
        gate(&g_done[0][b]);
        level_tile<2, 18, 72>(out + (size_t)(4 * b + 3) * CHS,
                              out + (size_t)(4 * b + 1) * CHS,
                              g_scratch + (size_t)b * CHS, B);
        finish(&g_done[1][b]);
    } else {
        gate(&g_done[1][b]);
        level_tile<4, 20, 80>(g_scratch + (size_t)b * CHS,
                              out + (size_t)(4 * b + 2) * CHS,
                              out + (size_t)(4 * b + 3) * CHS, B);
        __threadfence();
        __syncthreads();
        if (threadIdx.x == 0) {
            if (atomicAdd(&g_done[2][b], 1u) == 255u) {
                atomicExch(&g_done[0][b], 0u);  // self-reset for next replay
                atomicExch(&g_done[1][b], 0u);
                atomicExch(&g_done[2][b], 0u);
            }
        }
    }
}

extern "C" void kernel_launch(void* const* d_in, const int* in_sizes, int n_in,
                              void* d_out, int out_size) {
    (void)in_sizes; (void)n_in; (void)out_size;
    const float* x = (const float*)d_in[0];
    float* out = (float*)d_out;

    dim3 grid(IMG / 64, IMG / 64, 24);  // z = level*8 + image
    uwt_all_kernel<<<grid, NT>>>(x, out);
}

// round 9
// speedup vs baseline: 1.1624x; 1.1624x over previous
#include <cuda_runtime.h>

// B3-spline à-trous UWT, J=3. ONE kernel launch: grid z = level*8 + image.
// (8,1024,1024) fp32 -> (8,4,1024,1024) fp32 = [w1,w2,w3,c3]
//
// Per block: one 64x64 tile of one level. Warp-autonomous 8-row strips.
// Phase 1 (vertical conv): batched chains — each unit loads ALL L+4 input
// rows of its chain as independent LDG.128s (high MLP), then computes the L
// outputs with compile-time taps. 36/36/80 units -> all 32 lanes active.
// Load redundancy 1.33x (D=1) / 1.0x (D=2,4). Phase 2: horizontal conv from
// smem + diff + coalesced store.
// Levels synchronize via per-image release/acquire counters (bid-ordered
// dispatch -> deadlock-free; counters self-reset -> graph-replay safe).
// c1 lives in out ch3 (overwritten by c3), c2 in a static scratch buffer.

namespace {

constexpr int NT  = 256;
constexpr int IMG = 1024;
constexpr size_t CHS = (size_t)IMG * IMG;

constexpr float W0 = 0.0625f;
constexpr float W1 = 0.25f;
constexpr float W2 = 0.375f;

__device__ float g_scratch[8u * 1024u * 1024u];  // 32MB c2 carrier
__device__ unsigned g_done[3][8];                // zero-init; self-resetting

__device__ __forceinline__ int refl(int g) {
    g = g < 0 ? -g : g;
    return g >= IMG ? 2 * IMG - 2 - g : g;
}
__device__ __forceinline__ float b3s(float a, float b, float c, float d, float e) {
    return fmaf(c, W2, fmaf(b + d, W1, (a + e) * W0));
}
__device__ __forceinline__ float4 b3v(const float4& a, const float4& b,
                                      const float4& c, const float4& d,
                                      const float4& e) {
    float4 r;
    r.x = b3s(a.x, b.x, c.x, d.x, e.x);
    r.y = b3s(a.y, b.y, c.y, d.y, e.y);
    r.z = b3s(a.z, b.z, c.z, d.z, e.z);
    r.w = b3s(a.w, b.w, c.w, d.w, e.w);
    return r;
}
__device__ __forceinline__ void st4(float* p, float4 v) {
    *reinterpret_cast<float4*>(p) = v;
}
__device__ __forceinline__ float4 ld4(const float* p) {
    return *reinterpret_cast<const float4*>(p);
}
__device__ __forceinline__ float4 lg4(const float* p) {
    return __ldg(reinterpret_cast<const float4*>(p));
}
__device__ __forceinline__ float4 gath(const float* row, const int cc[4]) {
    return make_float4(__ldg(row + cc[0]), __ldg(row + cc[1]),
                       __ldg(row + cc[2]), __ldg(row + cc[3]));
}

// One 64x64 tile of one level, dilation D. H = col halo (4 for D<=2, else
// 2D; 16B-aligned), NVEC = (64+2H)/4 vec-cols, PB = smem row pitch.
template <int D, int NVEC, int PB>
__device__ __forceinline__ void level_tile(const float* __restrict__ s,
                                           float* __restrict__ wd,
                                           float* __restrict__ cd,
                                           float* __restrict__ B) {
    const int tid  = threadIdx.x;
    const int lane = tid & 31;
    const int warp = tid >> 5;
    const int gc0 = blockIdx.x * 64;
    const int gr0 = blockIdx.y * 64;
    const int wr0 = gr0 + warp * 8;
    float* Bw = B + warp * (8 * PB);
    constexpr int H = (D == 1) ? 4 : 2 * D;
    const bool colint = (gc0 >= H) && (gc0 + 64 + H <= IMG);

    // ---- phase 1: vertical conv, batched chains ----
    constexpr int L   = (D == 4) ? 2 : 4;   // outputs per chain
    constexpr int CPC = 8 / L;              // chains per column (2/2/4)
    constexpr int UNITS = NVEC * CPC;       // 36 / 36 / 80
    constexpr int NLD = L + 4;              // rows loaded per chain
    for (int u = lane; u < UNITS; u += 32) {
        const int vc = u % NVEC;
        const int t  = u / NVEC;
        // D==1: contiguous segments; D>=2: dilation phase chains
        const int r0 = (D == 1) ? t * L : t;   // first output row (local)
        const int cb = gc0 - H + 4 * vc;
        float4 in[NLD];
        if (colint) {
            const float* cp = s + cb;
#pragma unroll
            for (int i = 0; i < NLD; ++i)
                in[i] = lg4(cp + (size_t)refl(wr0 + r0 + (i - 2) * D) * IMG);
        } else {
            int cc[4];
#pragma unroll
            for (int j = 0; j < 4; ++j) {
                int c = cb + j;
                c = c < 0 ? -c : c;
                cc[j] = c >= IMG ? 2 * IMG - 2 - c : c;
            }
#pragma unroll
            for (int i = 0; i < NLD; ++i)
                in[i] = gath(s + (size_t)refl(wr0 + r0 + (i - 2) * D) * IMG, cc);
        }
        float* Bp = Bw + 4 * vc;
#pragma unroll
        for (int k = 0; k < L; ++k)
            st4(Bp + (r0 + k * D) * PB,
                b3v(in[k], in[k + 1], in[k + 2], in[k + 3], in[k + 4]));
    }
    __syncwarp();

    // ---- phase 2: horizontal conv + diff + coalesced store ----
    const int v = lane & 15, sub = lane >> 4;
    constexpr int BL = H / 4;
    constexpr int NV = 2 * BL + 1;      // window float4 count (3/3/5)
    constexpr int C  = H;               // center float offset in window
#pragma unroll
    for (int i = 0; i < 4; ++i) {
        const int rr = i * 2 + sub;
        const float* Bp = Bw + rr * PB + 4 * v;
        float w[4 * NV];
#pragma unroll
        for (int k = 0; k < NV; ++k) {
            const float4 t = ld4(Bp + 4 * k);
            w[4 * k + 0] = t.x; w[4 * k + 1] = t.y;
            w[4 * k + 2] = t.z; w[4 * k + 3] = t.w;
        }
        float4 o;
        o.x = b3s(w[C - 2 * D],     w[C - D],     w[C],     w[C + D],     w[C + 2 * D]);
        o.y = b3s(w[C + 1 - 2 * D], w[C + 1 - D], w[C + 1], w[C + 1 + D], w[C + 1 + 2 * D]);
        o.z = b3s(w[C + 2 - 2 * D], w[C + 2 - D], w[C + 2], w[C + 2 + D], w[C + 2 + 2 * D]);
        o.w = b3s(w[C + 3 - 2 * D], w[C + 3 - D], w[C + 3], w[C + 3 + D], w[C + 3 + 2 * D]);

        const size_t go = (size_t)(wr0 + rr) * IMG + gc0 + 4 * v;
        const float4 a = lg4(s + go);
        st4(wd + go, make_float4(a.x - o.x, a.y - o.y, a.z - o.z, a.w - o.w));
        st4(cd + go, o);
    }
}

__device__ __forceinline__ void gate(unsigned* ctr) {
    if (threadIdx.x == 0) {
        while (atomicAdd(ctr, 0u) < 256u) __nanosleep(64);
        __threadfence();
    }
    __syncthreads();
}
__device__ __forceinline__ void finish(unsigned* ctr) {
    __threadfence();
    __syncthreads();
    if (threadIdx.x == 0) atomicAdd(ctr, 1u);
}

}  // namespace

__global__ void __launch_bounds__(NT, 5)
uwt_all_kernel(const float* __restrict__ x, float* __restrict__ out) {
    __shared__ float B[8 * 8 * 80];  // max strip pitch (D=4)
    const int z = blockIdx.z;
    const int l = z >> 3;
    const int b = z & 7;

    if (l == 0) {
        level_tile<1, 18, 72>(x + (size_t)b * CHS,
                              out + (size_t)(4 * b + 0) * CHS,
                              out + (size_t)(4 * b + 3) * CHS, B);
        finish(&g_done[0][b]);
    } else if (l == 1) {
        gate(&g_done[0][b]);
        level_tile<2, 18, 72>(out + (size_t)(4 * b + 3) * CHS,
                              out + (size_t)(4 * b + 1) * CHS,
                              g_scratch + (size_t)b * CHS, B);
        finish(&g_done[1][b]);
    } else {
        gate(&g_done[1][b]);
        level_tile<4, 20, 80>(g_scratch + (size_t)b * CHS,
                              out + (size_t)(4 * b + 2) * CHS,
                              out + (size_t)(4 * b + 3) * CHS, B);
        __threadfence();
        __syncthreads();
        if (threadIdx.x == 0) {
            if (atomicAdd(&g_done[2][b], 1u) == 255u) {
                atomicExch(&g_done[0][b], 0u);  // self-reset for next replay
                atomicExch(&g_done[1][b], 0u);
                atomicExch(&g_done[2][b], 0u);
            }
        }
    }
}

extern "C" void kernel_launch(void* const* d_in, const int* in_sizes, int n_in,
                              void* d_out, int out_size) {
    (void)in_sizes; (void)n_in; (void)out_size;
    const float* x = (const float*)d_in[0];
    float* out = (float*)d_out;

    dim3 grid(IMG / 64, IMG / 64, 24);  // z = level*8 + image
    uwt_all_kernel<<<grid, NT>>>(x, out);
}